// round 1
// baseline (speedup 1.0000x reference)
#include <cuda_runtime.h>
#include <math.h>

// Problem constants
#define BATCH   8
#define SEQ     2048
#define DIM     512           // INPUT_DIM == HIDDEN_DIM == 512
#define BS      (BATCH * SEQ) // 16384
#define YSIZE   ((size_t)BS * DIM)         // 8,388,608
#define ATTNSZ  ((size_t)BATCH * SEQ * SEQ)

// Scratch (alloc-free: __device__ globals)
__device__ __align__(16) float g_q[BS * DIM];
__device__ __align__(16) float g_k[BS * DIM];
__device__ __align__(16) float g_v[BS * DIM];
__device__ __align__(16) float g_o[BS * DIM];
__device__ __align__(16) float g_y[BS * DIM];

// ---------------------------------------------------------------------------
// Generic tiled SGEMM: C = scale * A @ B (+ bias[col]) (+ residual[row,col])
//   A: M x K row-major
//   B: TRANSB ? (N x K row-major, i.e. B^T used)  :  (K x N row-major)
//   C: M x N row-major
// blockIdx.z batches with given strides.
// Tile: 128x128x8, 256 threads, 8x8 per-thread microtile.
// All dims assumed divisible by tile sizes (true for this problem).
// ---------------------------------------------------------------------------
template <bool TRANSB>
__global__ __launch_bounds__(256)
void sgemm_kernel(const float* __restrict__ A,
                  const float* __restrict__ B,
                  float* __restrict__ C,
                  int M, int N, int K,
                  long strideA, long strideB, long strideC,
                  float scale,
                  const float* __restrict__ bias,
                  const float* __restrict__ residual)
{
    constexpr int BM = 128, BN = 128, BK = 8;
    __shared__ __align__(16) float As[BK][BM];
    __shared__ __align__(16) float Bs[BK][BN];

    A += (long)blockIdx.z * strideA;
    B += (long)blockIdx.z * strideB;
    C += (long)blockIdx.z * strideC;
    if (residual) residual += (long)blockIdx.z * strideC;

    const int block_row = blockIdx.y * BM;
    const int block_col = blockIdx.x * BN;

    const int t  = threadIdx.x;     // 0..255
    const int ty = t >> 4;          // 0..15
    const int tx = t & 15;          // 0..15

    // A loader: each thread loads one float4 of A tile (128 rows x 8 cols)
    const int a_row = t >> 1;         // 0..127
    const int a_col = (t & 1) * 4;    // 0 or 4
    // B (NN) loader: tile is 8 rows x 128 cols
    const int b_row = t >> 5;         // 0..7
    const int b_col = (t & 31) * 4;   // 0..124

    float acc[8][8];
#pragma unroll
    for (int i = 0; i < 8; i++)
#pragma unroll
        for (int j = 0; j < 8; j++) acc[i][j] = 0.f;

    for (int k0 = 0; k0 < K; k0 += BK) {
        // ---- load A tile (transposed into As[k][m]) ----
        float4 av = *reinterpret_cast<const float4*>(
            &A[(long)(block_row + a_row) * K + k0 + a_col]);
        As[a_col + 0][a_row] = av.x;
        As[a_col + 1][a_row] = av.y;
        As[a_col + 2][a_row] = av.z;
        As[a_col + 3][a_row] = av.w;

        // ---- load B tile into Bs[k][n] ----
        if (TRANSB) {
            // B is N x K row-major; want Bs[k][n] = B[n][k]
            float4 bv = *reinterpret_cast<const float4*>(
                &B[(long)(block_col + a_row) * K + k0 + a_col]);
            Bs[a_col + 0][a_row] = bv.x;
            Bs[a_col + 1][a_row] = bv.y;
            Bs[a_col + 2][a_row] = bv.z;
            Bs[a_col + 3][a_row] = bv.w;
        } else {
            float4 bv = *reinterpret_cast<const float4*>(
                &B[(long)(k0 + b_row) * N + block_col + b_col]);
            *reinterpret_cast<float4*>(&Bs[b_row][b_col]) = bv;
        }
        __syncthreads();

#pragma unroll
        for (int kk = 0; kk < BK; kk++) {
            float af[8], bf[8];
#pragma unroll
            for (int i = 0; i < 8; i++) af[i] = As[kk][ty * 8 + i];
#pragma unroll
            for (int j = 0; j < 8; j++) bf[j] = Bs[kk][tx * 8 + j];
#pragma unroll
            for (int i = 0; i < 8; i++)
#pragma unroll
                for (int j = 0; j < 8; j++)
                    acc[i][j] = fmaf(af[i], bf[j], acc[i][j]);
        }
        __syncthreads();
    }

    // ---- epilogue ----
#pragma unroll
    for (int i = 0; i < 8; i++) {
        const long row = block_row + ty * 8 + i;
#pragma unroll
        for (int j = 0; j < 8; j++) {
            const int col = block_col + tx * 8 + j;
            float c = acc[i][j] * scale;
            if (bias)     c += bias[col];
            if (residual) c += residual[row * N + col];
            C[row * N + col] = c;
        }
    }
}

// ---------------------------------------------------------------------------
// In-place row softmax over the attn slab. One block (256 thr) per row of 2048.
// ---------------------------------------------------------------------------
__global__ __launch_bounds__(256)
void softmax_kernel(float* __restrict__ attn)
{
    const long row = blockIdx.x;
    float* p = attn + row * (long)SEQ;
    const int t = threadIdx.x;

    float v[8];
    float m = -INFINITY;
#pragma unroll
    for (int i = 0; i < 8; i++) {
        v[i] = p[t + i * 256];
        m = fmaxf(m, v[i]);
    }

    __shared__ float sh[8];
    const int lane = t & 31, warp = t >> 5;

    // block max
#pragma unroll
    for (int o = 16; o; o >>= 1) m = fmaxf(m, __shfl_xor_sync(0xffffffffu, m, o));
    if (lane == 0) sh[warp] = m;
    __syncthreads();
    float bm = sh[0];
#pragma unroll
    for (int i = 1; i < 8; i++) bm = fmaxf(bm, sh[i]);
    __syncthreads();

    // exp + block sum
    float s = 0.f;
#pragma unroll
    for (int i = 0; i < 8; i++) {
        v[i] = __expf(v[i] - bm);
        s += v[i];
    }
#pragma unroll
    for (int o = 16; o; o >>= 1) s += __shfl_xor_sync(0xffffffffu, s, o);
    if (lane == 0) sh[warp] = s;
    __syncthreads();
    float bs = 0.f;
#pragma unroll
    for (int i = 0; i < 8; i++) bs += sh[i];

    const float inv = 1.0f / bs;
#pragma unroll
    for (int i = 0; i < 8; i++) p[t + i * 256] = v[i] * inv;
}

// ---------------------------------------------------------------------------
// LayerNorm: one block (128 thr) per row of 512; float4 per thread.
// ---------------------------------------------------------------------------
__global__ __launch_bounds__(128)
void layernorm_kernel(const float* __restrict__ ypre,
                      const float* __restrict__ gamma,
                      const float* __restrict__ beta,
                      float* __restrict__ out)
{
    const long row = blockIdx.x;
    const int t = threadIdx.x;
    const float4 v = reinterpret_cast<const float4*>(ypre + row * DIM)[t];

    float s  = v.x + v.y + v.z + v.w;
    float ss = v.x * v.x + v.y * v.y + v.z * v.z + v.w * v.w;

    __shared__ float shs[4], shss[4];
    const int lane = t & 31, warp = t >> 5;
#pragma unroll
    for (int o = 16; o; o >>= 1) {
        s  += __shfl_xor_sync(0xffffffffu, s,  o);
        ss += __shfl_xor_sync(0xffffffffu, ss, o);
    }
    if (lane == 0) { shs[warp] = s; shss[warp] = ss; }
    __syncthreads();
    float bsum = shs[0] + shs[1] + shs[2] + shs[3];
    float bssq = shss[0] + shss[1] + shss[2] + shss[3];

    const float mean = bsum * (1.0f / DIM);
    const float var  = bssq * (1.0f / DIM) - mean * mean;
    const float inv  = rsqrtf(var + 1e-5f);

    const float4 g = reinterpret_cast<const float4*>(gamma)[t];
    const float4 b = reinterpret_cast<const float4*>(beta)[t];
    float4 o;
    o.x = (v.x - mean) * inv * g.x + b.x;
    o.y = (v.y - mean) * inv * g.y + b.y;
    o.z = (v.z - mean) * inv * g.z + b.z;
    o.w = (v.w - mean) * inv * g.w + b.w;
    reinterpret_cast<float4*>(out + row * DIM)[t] = o;
}

// ---------------------------------------------------------------------------
extern "C" void kernel_launch(void* const* d_in, const int* in_sizes, int n_in,
                              void* d_out, int out_size)
{
    const float* x     = (const float*)d_in[0];
    const float* Wq    = (const float*)d_in[1];
    const float* bq    = (const float*)d_in[2];
    const float* Wk    = (const float*)d_in[3];
    const float* bk    = (const float*)d_in[4];
    const float* Wv    = (const float*)d_in[5];
    const float* bv    = (const float*)d_in[6];
    const float* Wp    = (const float*)d_in[7];
    const float* bp    = (const float*)d_in[8];
    const float* gamma = (const float*)d_in[9];
    const float* beta  = (const float*)d_in[10];

    float* y_out = (float*)d_out;
    float* attn  = y_out + YSIZE;

    float *gq, *gk, *gv, *go, *gy;
    cudaGetSymbolAddress((void**)&gq, g_q);
    cudaGetSymbolAddress((void**)&gk, g_k);
    cudaGetSymbolAddress((void**)&gv, g_v);
    cudaGetSymbolAddress((void**)&go, g_o);
    cudaGetSymbolAddress((void**)&gy, g_y);

    const float inv_sqrt_h = 1.0f / sqrtf((float)DIM);

    // QKV projections: (16384x512) @ (512x512) + bias
    {
        dim3 grid(DIM / 128, BS / 128, 1);
        sgemm_kernel<false><<<grid, 256>>>(x, Wq, gq, BS, DIM, DIM, 0, 0, 0, 1.f, bq, nullptr);
        sgemm_kernel<false><<<grid, 256>>>(x, Wk, gk, BS, DIM, DIM, 0, 0, 0, 1.f, bk, nullptr);
        sgemm_kernel<false><<<grid, 256>>>(x, Wv, gv, BS, DIM, DIM, 0, 0, 0, 1.f, bv, nullptr);
    }

    // scores = Q @ K^T / sqrt(H), written raw into attn output slab
    {
        dim3 grid(SEQ / 128, SEQ / 128, BATCH);
        sgemm_kernel<true><<<grid, 256>>>(gq, gk, attn,
                                          SEQ, SEQ, DIM,
                                          (long)SEQ * DIM, (long)SEQ * DIM, (long)SEQ * SEQ,
                                          inv_sqrt_h, nullptr, nullptr);
    }

    // in-place softmax over each of the 8*2048 rows
    softmax_kernel<<<BATCH * SEQ, 256>>>(attn);

    // O = P @ V
    {
        dim3 grid(DIM / 128, SEQ / 128, BATCH);
        sgemm_kernel<false><<<grid, 256>>>(attn, gv, go,
                                           SEQ, DIM, SEQ,
                                           (long)SEQ * SEQ, (long)SEQ * DIM, (long)SEQ * DIM,
                                           1.f, nullptr, nullptr);
    }

    // Ypre = O @ Wp + bp + x   (residual fused in epilogue)
    {
        dim3 grid(DIM / 128, BS / 128, 1);
        sgemm_kernel<false><<<grid, 256>>>(go, Wp, gy, BS, DIM, DIM, 0, 0, 0, 1.f, bp, x);
    }

    // LayerNorm -> y output
    layernorm_kernel<<<BATCH * SEQ, 128>>>(gy, gamma, beta, y_out);
}

// round 3
// speedup vs baseline: 3.0981x; 3.0981x over previous
#include <cuda_runtime.h>
#include <math.h>
#include <stdint.h>

// ---------------------------------------------------------------------------
// Problem constants
// ---------------------------------------------------------------------------
#define BATCH   8
#define SEQ     2048
#define DIM     512
#define BS      (BATCH * SEQ)          // 16384
#define YSIZE   ((size_t)BS * DIM)     // 8,388,608

// Scratch (alloc-free: __device__ globals)
__device__ __align__(16) float g_q [BS * DIM];
__device__ __align__(16) float g_k [BS * DIM];
__device__ __align__(16) float g_v [BS * DIM];
__device__ __align__(16) float g_vt[BS * DIM];          // per-batch V^T
__device__ __align__(16) float g_o [BS * DIM];
__device__ __align__(16) float g_y [BS * DIM];
__device__ __align__(16) float g_wt[4][DIM * DIM];      // WqT, WkT, WvT, WpT

// ---------------------------------------------------------------------------
// helpers
// ---------------------------------------------------------------------------
__device__ __forceinline__ uint32_t smem_u32(const void* p) {
    uint32_t a;
    asm("{ .reg .u64 t; cvta.to.shared.u64 t, %1; cvt.u32.u64 %0, t; }"
        : "=r"(a) : "l"(p));
    return a;
}
__device__ __forceinline__ uint32_t f2tf32(float f) {
    uint32_t r;
    asm("cvt.rna.tf32.f32 %0, %1;" : "=r"(r) : "f"(f));
    return r;
}
__device__ __forceinline__ void ldmatrix4(uint32_t& r0, uint32_t& r1,
                                          uint32_t& r2, uint32_t& r3,
                                          uint32_t addr) {
    asm volatile("ldmatrix.sync.aligned.m8n8.x4.shared.b16 {%0,%1,%2,%3}, [%4];"
                 : "=r"(r0), "=r"(r1), "=r"(r2), "=r"(r3) : "r"(addr));
}
__device__ __forceinline__ void mma_tf32(float* c, const uint32_t* a,
                                         const uint32_t* b) {
    asm volatile(
        "mma.sync.aligned.m16n8k8.row.col.f32.tf32.tf32.f32 "
        "{%0,%1,%2,%3}, {%4,%5,%6,%7}, {%8,%9}, {%0,%1,%2,%3};"
        : "+f"(c[0]), "+f"(c[1]), "+f"(c[2]), "+f"(c[3])
        : "r"(a[0]), "r"(a[1]), "r"(a[2]), "r"(a[3]), "r"(b[0]), "r"(b[1]));
}

// ---------------------------------------------------------------------------
// tf32 mma.sync GEMM:  C[M,N] = scale * A[M,K] @ B[N,K]^T (+bias[col]) (+resid)
// A: row-major [M,K]; B: row-major [N,K] (i.e. TN GEMM). C row-major [M,N].
// CTA tile 128x128, BK=32, 256 threads (8 warps as 2m x 4n, warp tile 64x32).
// SMEM tiles XOR-swizzled at float4 granularity; fragments via ldmatrix.
// blockIdx.z batches via strides. M,N multiples of 128, K multiple of 32.
// ---------------------------------------------------------------------------
#define TILE_BYTES 16384          // 128 rows * 32 floats * 4
#define SMEM_TOTAL (4 * TILE_BYTES)   // A0,B0,A1,B1

__global__ __launch_bounds__(256)
void tc_gemm(const float* __restrict__ A, const float* __restrict__ B,
             float* __restrict__ C,
             int N, int K,
             long sA, long sB, long sC,
             float scale, const float* __restrict__ bias,
             const float* __restrict__ resid)
{
    extern __shared__ char smem[];
    const uint32_t sb = smem_u32(smem);

    const int t    = threadIdx.x;
    const int wid  = t >> 5;
    const int lane = t & 31;
    const int wm   = wid >> 2;           // 0..1
    const int wn   = wid & 3;            // 0..3

    A += (long)blockIdx.z * sA;
    B += (long)blockIdx.z * sB;
    C += (long)blockIdx.z * sC;
    if (resid) resid += (long)blockIdx.z * sC;

    const long brow = (long)blockIdx.y * 128;
    const long bcol = (long)blockIdx.x * 128;

    // ---- loader indices ----
    const int lrow   = t >> 3;            // 0..31 (4 passes of +32)
    const int lchunk = t & 7;             // float4 chunk in a 32-float row

    // ---- ldmatrix per-thread bases ----
    const int r7     = lane & 7;
    const int rowA   = wm * 64 + (lane & 7) + ((lane >> 3) & 1) * 8;
    const int khalfA = lane >> 4;                    // 0/1
    const int rowB   = wn * 32 + (lane & 7) + ((lane >> 4) & 1) * 8;
    const int khalfB = (lane >> 3) & 1;              // 0/1

    float c[4][4][4];
#pragma unroll
    for (int i = 0; i < 4; i++)
#pragma unroll
        for (int j = 0; j < 4; j++)
#pragma unroll
            for (int k = 0; k < 4; k++) c[i][j][k] = 0.f;

    const int NCH = K >> 5;

    // ---- prologue: load chunk 0 into buffer 0 ----
    {
        const uint32_t sA0 = sb;
        const uint32_t sB0 = sb + TILE_BYTES;
#pragma unroll
        for (int i = 0; i < 4; i++) {
            const int r = lrow + i * 32;
            float4 va = *reinterpret_cast<const float4*>(
                A + (brow + r) * (long)K + lchunk * 4);
            float4 vb = *reinterpret_cast<const float4*>(
                B + (bcol + r) * (long)K + lchunk * 4);
            const uint32_t off = (uint32_t)(r * 8 + (lchunk ^ (r & 7))) * 16;
            uint32_t a0 = f2tf32(va.x), a1 = f2tf32(va.y),
                     a2 = f2tf32(va.z), a3 = f2tf32(va.w);
            asm volatile("st.shared.v4.b32 [%0], {%1,%2,%3,%4};"
                         :: "r"(sA0 + off), "r"(a0), "r"(a1), "r"(a2), "r"(a3));
            uint32_t b0 = f2tf32(vb.x), b1 = f2tf32(vb.y),
                     b2 = f2tf32(vb.z), b3 = f2tf32(vb.w);
            asm volatile("st.shared.v4.b32 [%0], {%1,%2,%3,%4};"
                         :: "r"(sB0 + off), "r"(b0), "r"(b1), "r"(b2), "r"(b3));
        }
    }
    __syncthreads();

    for (int ch = 0; ch < NCH; ch++) {
        const int cur = ch & 1;
        const uint32_t saA = sb + cur * 2 * TILE_BYTES;
        const uint32_t saB = saA + TILE_BYTES;

        // ---- prefetch next chunk into registers ----
        float4 pa[4], pb[4];
        const bool have_next = (ch + 1) < NCH;
        if (have_next) {
            const long k0 = (long)(ch + 1) << 5;
#pragma unroll
            for (int i = 0; i < 4; i++) {
                const int r = lrow + i * 32;
                pa[i] = *reinterpret_cast<const float4*>(
                    A + (brow + r) * (long)K + k0 + lchunk * 4);
                pb[i] = *reinterpret_cast<const float4*>(
                    B + (bcol + r) * (long)K + k0 + lchunk * 4);
            }
        }

        // ---- compute on current buffer ----
        const uint32_t baseA = saA + (uint32_t)(rowA * 128);
        const uint32_t baseB = saB + (uint32_t)(rowB * 128);
#pragma unroll
        for (int ks = 0; ks < 4; ks++) {
            uint32_t a[4][4];
#pragma unroll
            for (int mt = 0; mt < 4; mt++) {
                const uint32_t addr = baseA + mt * 2048u
                                    + (uint32_t)(((2 * ks + khalfA) ^ r7) * 16);
                ldmatrix4(a[mt][0], a[mt][1], a[mt][2], a[mt][3], addr);
            }
            uint32_t b[4][2];
#pragma unroll
            for (int p = 0; p < 2; p++) {
                const uint32_t addr = baseB + p * 2048u
                                    + (uint32_t)(((2 * ks + khalfB) ^ r7) * 16);
                ldmatrix4(b[2 * p][0], b[2 * p][1],
                          b[2 * p + 1][0], b[2 * p + 1][1], addr);
            }
#pragma unroll
            for (int mt = 0; mt < 4; mt++)
#pragma unroll
                for (int nt = 0; nt < 4; nt++)
                    mma_tf32(c[mt][nt], a[mt], b[nt]);
        }

        // ---- store prefetched chunk ----
        if (have_next) {
            const uint32_t sdA = sb + ((ch + 1) & 1) * 2 * TILE_BYTES;
            const uint32_t sdB = sdA + TILE_BYTES;
#pragma unroll
            for (int i = 0; i < 4; i++) {
                const int r = lrow + i * 32;
                const uint32_t off = (uint32_t)(r * 8 + (lchunk ^ (r & 7))) * 16;
                uint32_t x0 = f2tf32(pa[i].x), x1 = f2tf32(pa[i].y),
                         x2 = f2tf32(pa[i].z), x3 = f2tf32(pa[i].w);
                asm volatile("st.shared.v4.b32 [%0], {%1,%2,%3,%4};"
                             :: "r"(sdA + off), "r"(x0), "r"(x1), "r"(x2), "r"(x3));
                uint32_t y0 = f2tf32(pb[i].x), y1 = f2tf32(pb[i].y),
                         y2 = f2tf32(pb[i].z), y3 = f2tf32(pb[i].w);
                asm volatile("st.shared.v4.b32 [%0], {%1,%2,%3,%4};"
                             :: "r"(sdB + off), "r"(y0), "r"(y1), "r"(y2), "r"(y3));
            }
        }
        __syncthreads();
    }

    // ---- epilogue: direct coalesced float2 stores from fragments ----
    const int g   = lane >> 2;           // 0..7
    const int tig = lane & 3;            // 0..3
#pragma unroll
    for (int mt = 0; mt < 4; mt++) {
        const long row0 = brow + wm * 64 + mt * 16 + g;
#pragma unroll
        for (int nt = 0; nt < 4; nt++) {
            const long col = bcol + wn * 32 + nt * 8 + 2 * tig;
            float bx = 0.f, by = 0.f;
            if (bias) {
                float2 bb = *reinterpret_cast<const float2*>(&bias[col]);
                bx = bb.x; by = bb.y;
            }
            {
                float vx = c[mt][nt][0] * scale + bx;
                float vy = c[mt][nt][1] * scale + by;
                if (resid) {
                    float2 rr = *reinterpret_cast<const float2*>(
                        &resid[row0 * N + col]);
                    vx += rr.x; vy += rr.y;
                }
                float2 o; o.x = vx; o.y = vy;
                *reinterpret_cast<float2*>(&C[row0 * N + col]) = o;
            }
            {
                const long row1 = row0 + 8;
                float vx = c[mt][nt][2] * scale + bx;
                float vy = c[mt][nt][3] * scale + by;
                if (resid) {
                    float2 rr = *reinterpret_cast<const float2*>(
                        &resid[row1 * N + col]);
                    vx += rr.x; vy += rr.y;
                }
                float2 o; o.x = vx; o.y = vy;
                *reinterpret_cast<float2*>(&C[row1 * N + col]) = o;
            }
        }
    }
}

// ---------------------------------------------------------------------------
// Tiled transpose: dst[c][r] = src[r][c], per-z slab of R x C floats.
// block (32,8), grid (C/32, R/32, Z)
// ---------------------------------------------------------------------------
__global__ __launch_bounds__(256)
void transpose_kernel(const float* __restrict__ src, float* __restrict__ dst,
                      int R, int C)
{
    __shared__ float tile[32][33];
    const long z = blockIdx.z;
    src += z * (long)R * C;
    dst += z * (long)R * C;
    const int bx = blockIdx.x * 32;
    const int by = blockIdx.y * 32;
    const int tx = threadIdx.x, ty = threadIdx.y;
#pragma unroll
    for (int i = 0; i < 32; i += 8)
        tile[ty + i][tx] = src[(long)(by + ty + i) * C + bx + tx];
    __syncthreads();
#pragma unroll
    for (int i = 0; i < 32; i += 8)
        dst[(long)(bx + ty + i) * R + by + tx] = tile[tx][ty + i];
}

// ---------------------------------------------------------------------------
// In-place row softmax (rows of 2048), one 256-thread block per row
// ---------------------------------------------------------------------------
__global__ __launch_bounds__(256)
void softmax_kernel(float* __restrict__ attn)
{
    const long row = blockIdx.x;
    float* p = attn + row * (long)SEQ;
    const int t = threadIdx.x;

    float v[8];
    float m = -INFINITY;
#pragma unroll
    for (int i = 0; i < 8; i++) { v[i] = p[t + i * 256]; m = fmaxf(m, v[i]); }

    __shared__ float sh[8];
    const int lane = t & 31, warp = t >> 5;
#pragma unroll
    for (int o = 16; o; o >>= 1) m = fmaxf(m, __shfl_xor_sync(0xffffffffu, m, o));
    if (lane == 0) sh[warp] = m;
    __syncthreads();
    float bm = sh[0];
#pragma unroll
    for (int i = 1; i < 8; i++) bm = fmaxf(bm, sh[i]);
    __syncthreads();

    float s = 0.f;
#pragma unroll
    for (int i = 0; i < 8; i++) { v[i] = __expf(v[i] - bm); s += v[i]; }
#pragma unroll
    for (int o = 16; o; o >>= 1) s += __shfl_xor_sync(0xffffffffu, s, o);
    if (lane == 0) sh[warp] = s;
    __syncthreads();
    float bs = 0.f;
#pragma unroll
    for (int i = 0; i < 8; i++) bs += sh[i];

    const float inv = 1.0f / bs;
#pragma unroll
    for (int i = 0; i < 8; i++) p[t + i * 256] = v[i] * inv;
}

// ---------------------------------------------------------------------------
// LayerNorm: one 128-thread block per row of 512, float4 per thread
// ---------------------------------------------------------------------------
__global__ __launch_bounds__(128)
void layernorm_kernel(const float* __restrict__ ypre,
                      const float* __restrict__ gamma,
                      const float* __restrict__ beta,
                      float* __restrict__ out)
{
    const long row = blockIdx.x;
    const int t = threadIdx.x;
    const float4 v = reinterpret_cast<const float4*>(ypre + row * DIM)[t];

    float s  = v.x + v.y + v.z + v.w;
    float ss = v.x * v.x + v.y * v.y + v.z * v.z + v.w * v.w;

    __shared__ float shs[4], shss[4];
    const int lane = t & 31, warp = t >> 5;
#pragma unroll
    for (int o = 16; o; o >>= 1) {
        s  += __shfl_xor_sync(0xffffffffu, s,  o);
        ss += __shfl_xor_sync(0xffffffffu, ss, o);
    }
    if (lane == 0) { shs[warp] = s; shss[warp] = ss; }
    __syncthreads();
    const float bsum = shs[0] + shs[1] + shs[2] + shs[3];
    const float bssq = shss[0] + shss[1] + shss[2] + shss[3];

    const float mean = bsum * (1.0f / DIM);
    const float var  = bssq * (1.0f / DIM) - mean * mean;
    const float inv  = rsqrtf(var + 1e-5f);

    const float4 g = reinterpret_cast<const float4*>(gamma)[t];
    const float4 b = reinterpret_cast<const float4*>(beta)[t];
    float4 o;
    o.x = (v.x - mean) * inv * g.x + b.x;
    o.y = (v.y - mean) * inv * g.y + b.y;
    o.z = (v.z - mean) * inv * g.z + b.z;
    o.w = (v.w - mean) * inv * g.w + b.w;
    reinterpret_cast<float4*>(out + row * DIM)[t] = o;
}

// ---------------------------------------------------------------------------
extern "C" void kernel_launch(void* const* d_in, const int* in_sizes, int n_in,
                              void* d_out, int out_size)
{
    const float* x     = (const float*)d_in[0];
    const float* Wq    = (const float*)d_in[1];
    const float* bq    = (const float*)d_in[2];
    const float* Wk    = (const float*)d_in[3];
    const float* bk    = (const float*)d_in[4];
    const float* Wv    = (const float*)d_in[5];
    const float* bv    = (const float*)d_in[6];
    const float* Wp    = (const float*)d_in[7];
    const float* bp    = (const float*)d_in[8];
    const float* gamma = (const float*)d_in[9];
    const float* beta  = (const float*)d_in[10];

    float* y_out = (float*)d_out;
    float* attn  = y_out + YSIZE;

    float *gq, *gk, *gv, *gvt, *go, *gy, *gwt;
    cudaGetSymbolAddress((void**)&gq,  g_q);
    cudaGetSymbolAddress((void**)&gk,  g_k);
    cudaGetSymbolAddress((void**)&gv,  g_v);
    cudaGetSymbolAddress((void**)&gvt, g_vt);
    cudaGetSymbolAddress((void**)&go,  g_o);
    cudaGetSymbolAddress((void**)&gy,  g_y);
    cudaGetSymbolAddress((void**)&gwt, g_wt);
    float* WqT = gwt;
    float* WkT = gwt + DIM * DIM;
    float* WvT = gwt + 2 * DIM * DIM;
    float* WpT = gwt + 3 * DIM * DIM;

    static int smem_set = 0;
    if (!smem_set) {
        cudaFuncSetAttribute(tc_gemm, cudaFuncAttributeMaxDynamicSharedMemorySize,
                             SMEM_TOTAL);
        smem_set = 1;
    }

    const float inv_sqrt_h = 1.0f / sqrtf((float)DIM);

    // ---- transpose weights to [N,K] form ----
    {
        dim3 blk(32, 8);
        dim3 grd(DIM / 32, DIM / 32, 1);
        transpose_kernel<<<grd, blk>>>(Wq, WqT, DIM, DIM);
        transpose_kernel<<<grd, blk>>>(Wk, WkT, DIM, DIM);
        transpose_kernel<<<grd, blk>>>(Wv, WvT, DIM, DIM);
        transpose_kernel<<<grd, blk>>>(Wp, WpT, DIM, DIM);
    }

    // ---- QKV projections ----
    {
        dim3 grid(DIM / 128, BS / 128, 1);
        tc_gemm<<<grid, 256, SMEM_TOTAL>>>(x, WqT, gq, DIM, DIM, 0, 0, 0, 1.f, bq, nullptr);
        tc_gemm<<<grid, 256, SMEM_TOTAL>>>(x, WkT, gk, DIM, DIM, 0, 0, 0, 1.f, bk, nullptr);
        tc_gemm<<<grid, 256, SMEM_TOTAL>>>(x, WvT, gv, DIM, DIM, 0, 0, 0, 1.f, bv, nullptr);
    }

    // ---- scores = Q @ K^T / sqrt(H) into attn slab ----
    {
        dim3 grid(SEQ / 128, SEQ / 128, BATCH);
        tc_gemm<<<grid, 256, SMEM_TOTAL>>>(gq, gk, attn, SEQ, DIM,
                                           (long)SEQ * DIM, (long)SEQ * DIM,
                                           (long)SEQ * SEQ,
                                           inv_sqrt_h, nullptr, nullptr);
    }

    // ---- softmax in place ----
    softmax_kernel<<<BATCH * SEQ, 256>>>(attn);

    // ---- V^T per batch ----
    {
        dim3 blk(32, 8);
        dim3 grd(DIM / 32, SEQ / 32, BATCH);
        transpose_kernel<<<grd, blk>>>(gv, gvt, SEQ, DIM);
    }

    // ---- O = P @ V  (B = V^T in [N,K] form) ----
    {
        dim3 grid(DIM / 128, SEQ / 128, BATCH);
        tc_gemm<<<grid, 256, SMEM_TOTAL>>>(attn, gvt, go, DIM, SEQ,
                                           (long)SEQ * SEQ, (long)SEQ * DIM,
                                           (long)SEQ * DIM,
                                           1.f, nullptr, nullptr);
    }

    // ---- Ypre = O @ Wp + bp + x (residual fused) ----
    {
        dim3 grid(DIM / 128, BS / 128, 1);
        tc_gemm<<<grid, 256, SMEM_TOTAL>>>(go, WpT, gy, DIM, DIM, 0, 0, 0,
                                           1.f, bp, x);
    }

    // ---- LayerNorm ----
    layernorm_kernel<<<BATCH * SEQ, 128>>>(gy, gamma, beta, y_out);
}

// round 5
// speedup vs baseline: 6.6595x; 2.1496x over previous
#include <cuda_runtime.h>
#include <cuda_fp16.h>
#include <math.h>
#include <stdint.h>

// ---------------------------------------------------------------------------
// Problem constants
// ---------------------------------------------------------------------------
#define BATCH   8
#define SEQ     2048
#define DIM     512
#define BS      (BATCH * SEQ)          // 16384
#define YSIZE   ((size_t)BS * DIM)     // 8,388,608

// Scratch (alloc-free: __device__ globals)
__device__ __align__(16) __half g_xh[BS * DIM];              // x in fp16
__device__ __align__(16) __half g_q [BS * DIM];
__device__ __align__(16) __half g_k [BS * DIM];
__device__ __align__(16) __half g_v [BS * DIM];
__device__ __align__(16) __half g_vt[BS * DIM];              // per-batch V^T
__device__ __align__(16) __half g_o [BS * DIM];
__device__ __align__(16) __half g_p [(size_t)BATCH * SEQ * SEQ]; // attn fp16
__device__ __align__(16) __half g_wt[4][DIM * DIM];          // W*T fp16
__device__ __align__(16) float  g_y [BS * DIM];

// ---------------------------------------------------------------------------
// helpers
// ---------------------------------------------------------------------------
__device__ __forceinline__ uint32_t smem_u32(const void* p) {
    uint32_t a;
    asm("{ .reg .u64 t; cvta.to.shared.u64 t, %1; cvt.u32.u64 %0, t; }"
        : "=r"(a) : "l"(p));
    return a;
}
__device__ __forceinline__ void ldmatrix4(uint32_t& r0, uint32_t& r1,
                                          uint32_t& r2, uint32_t& r3,
                                          uint32_t addr) {
    asm volatile("ldmatrix.sync.aligned.m8n8.x4.shared.b16 {%0,%1,%2,%3}, [%4];"
                 : "=r"(r0), "=r"(r1), "=r"(r2), "=r"(r3) : "r"(addr));
}
__device__ __forceinline__ void mma_f16(float* c, const uint32_t* a,
                                        const uint32_t* b) {
    asm volatile(
        "mma.sync.aligned.m16n8k16.row.col.f32.f16.f16.f32 "
        "{%0,%1,%2,%3}, {%4,%5,%6,%7}, {%8,%9}, {%0,%1,%2,%3};"
        : "+f"(c[0]), "+f"(c[1]), "+f"(c[2]), "+f"(c[3])
        : "r"(a[0]), "r"(a[1]), "r"(a[2]), "r"(a[3]), "r"(b[0]), "r"(b[1]));
}
__device__ __forceinline__ void cp16(uint32_t s, const void* g) {
    asm volatile("cp.async.cg.shared.global [%0], [%1], 16;" :: "r"(s), "l"(g));
}
#define CP_COMMIT() asm volatile("cp.async.commit_group;" ::: "memory")
#define CP_WAIT1()  asm volatile("cp.async.wait_group 1;" ::: "memory")

// ---------------------------------------------------------------------------
// fp16 mma.sync TN GEMM: C[M,N] = scale*A[M,K]@B[N,K]^T (+bias[col]) (+resid)
// A,B fp16 row-major (row stride K). C fp32 or fp16 (OUT_HALF), row stride N.
// CTA tile 128x128, BK=64, 256 threads = 8 warps (2m x 4n), warp tile 64x32.
// cp.async 2-stage pipeline. SMEM rows 128B, XOR-swizzled 16B chunks.
// blockIdx.z batches via strides. M,N mult of 128, K mult of 64.
// ---------------------------------------------------------------------------
#define STAGE_BYTES 32768   // A (16KB) + B (16KB)
#define SMEM_TOTAL  (2 * STAGE_BYTES)

template <bool OUT_HALF>
__global__ __launch_bounds__(256)
void hgemm(const __half* __restrict__ A,
           const __half* __restrict__ B,
           void* __restrict__ Cv,
           int N, int K,
           long sA, long sB, long sC,
           float scale, const float* __restrict__ bias,
           const float* __restrict__ resid)
{
    extern __shared__ char smem[];
    const uint32_t sb = smem_u32(smem);

    const int t    = threadIdx.x;
    const int wid  = t >> 5;
    const int lane = t & 31;
    const int wm   = wid >> 2;           // 0..1
    const int wn   = wid & 3;            // 0..3

    A += (long)blockIdx.z * sA;
    B += (long)blockIdx.z * sB;

    const long brow = (long)blockIdx.y * 128;
    const long bcol = (long)blockIdx.x * 128;

    const int lrow   = t >> 3;           // 0..31
    const int lchunk = t & 7;            // 16B chunk within 128B row

    const int r15   = lane & 15;
    const int khalf = lane >> 4;         // 0/1

    float c[4][4][4];
#pragma unroll
    for (int i = 0; i < 4; i++)
#pragma unroll
        for (int j = 0; j < 4; j++)
#pragma unroll
            for (int k = 0; k < 4; k++) c[i][j][k] = 0.f;

    const int NCH = K >> 6;              // K chunks of 64

    auto load_stage = [&](int ch, int s) {
        const __half* Ab = A + brow * K + (long)ch * 64;
        const __half* Bb = B + bcol * K + (long)ch * 64;
        const uint32_t sA_ = sb + s * STAGE_BYTES;
        const uint32_t sB_ = sA_ + 16384;
#pragma unroll
        for (int i = 0; i < 4; i++) {
            const int r = lrow + i * 32;
            const uint32_t off = (uint32_t)(r * 128 + ((lchunk ^ (r & 7)) * 16));
            cp16(sA_ + off, Ab + (long)r * K + lchunk * 8);
            cp16(sB_ + off, Bb + (long)r * K + lchunk * 8);
        }
    };

    load_stage(0, 0);
    CP_COMMIT();

    for (int ch = 0; ch < NCH; ch++) {
        if (ch + 1 < NCH) load_stage(ch + 1, (ch + 1) & 1);
        CP_COMMIT();
        CP_WAIT1();
        __syncthreads();

        const uint32_t saA = sb + (ch & 1) * STAGE_BYTES;
        const uint32_t saB = saA + 16384;

#pragma unroll
        for (int ks = 0; ks < 4; ks++) {
            uint32_t a[4][4];
#pragma unroll
            for (int mt = 0; mt < 4; mt++) {
                const int r = wm * 64 + mt * 16 + r15;
                const uint32_t ck = (uint32_t)((2 * ks + khalf) ^ (r & 7));
                ldmatrix4(a[mt][0], a[mt][1], a[mt][2], a[mt][3],
                          saA + (uint32_t)(r * 128) + ck * 16);
            }
            uint32_t br[2][4];
#pragma unroll
            for (int p = 0; p < 2; p++) {
                const int n = wn * 32 + p * 16 + r15;
                const uint32_t ck = (uint32_t)((2 * ks + khalf) ^ (n & 7));
                ldmatrix4(br[p][0], br[p][1], br[p][2], br[p][3],
                          saB + (uint32_t)(n * 128) + ck * 16);
            }
#pragma unroll
            for (int mt = 0; mt < 4; mt++)
#pragma unroll
                for (int nt = 0; nt < 4; nt++) {
                    uint32_t bb[2] = { br[nt >> 1][nt & 1], br[nt >> 1][(nt & 1) + 2] };
                    mma_f16(c[mt][nt], a[mt], bb);
                }
        }
        __syncthreads();
    }

    // ---- epilogue: direct coalesced stores from fragments ----
    const long cbz = (long)blockIdx.z * sC;
    const int g    = lane >> 2;          // 0..7
    const int tig  = lane & 3;           // 0..3
#pragma unroll
    for (int mt = 0; mt < 4; mt++) {
        const long row0 = brow + wm * 64 + mt * 16 + g;
#pragma unroll
        for (int nt = 0; nt < 4; nt++) {
            const long col = bcol + wn * 32 + nt * 8 + 2 * tig;
            float bx = 0.f, by = 0.f;
            if (bias) {
                float2 bb = *reinterpret_cast<const float2*>(&bias[col]);
                bx = bb.x; by = bb.y;
            }
#pragma unroll
            for (int h = 0; h < 2; h++) {
                const long row = row0 + h * 8;
                float vx = c[mt][nt][2 * h + 0] * scale + bx;
                float vy = c[mt][nt][2 * h + 1] * scale + by;
                if (resid) {
                    float2 rr = *reinterpret_cast<const float2*>(
                        &resid[cbz + row * N + col]);
                    vx += rr.x; vy += rr.y;
                }
                if (OUT_HALF) {
                    __half* C = (__half*)Cv;
                    *reinterpret_cast<__half2*>(&C[cbz + row * N + col]) =
                        __floats2half2_rn(vx, vy);
                } else {
                    float* C = (float*)Cv;
                    float2 o; o.x = vx; o.y = vy;
                    *reinterpret_cast<float2*>(&C[cbz + row * N + col]) = o;
                }
            }
        }
    }
}

// ---------------------------------------------------------------------------
// fp32 -> fp16 bulk convert
// ---------------------------------------------------------------------------
__global__ __launch_bounds__(256)
void cvt_h_kernel(const float* __restrict__ in,
                  __half* __restrict__ out, long n)
{
    const long i = ((long)blockIdx.x * 256 + threadIdx.x) * 4;
    if (i < n) {
        float4 v = *reinterpret_cast<const float4*>(in + i);
        *reinterpret_cast<__half2*>(out + i)     = __floats2half2_rn(v.x, v.y);
        *reinterpret_cast<__half2*>(out + i + 2) = __floats2half2_rn(v.z, v.w);
    }
}

// ---------------------------------------------------------------------------
// Transpose fp32 -> fp16 (weights):  dst[c][r] = h(src[r][c]);  R x C
// ---------------------------------------------------------------------------
__global__ __launch_bounds__(256)
void transpose_cvt_kernel(const float* __restrict__ src,
                          __half* __restrict__ dst, int R, int C)
{
    __shared__ float tile[32][33];
    const int bx = blockIdx.x * 32;
    const int by = blockIdx.y * 32;
    const int tx = threadIdx.x, ty = threadIdx.y;
#pragma unroll
    for (int i = 0; i < 32; i += 8)
        tile[ty + i][tx] = src[(long)(by + ty + i) * C + bx + tx];
    __syncthreads();
#pragma unroll
    for (int i = 0; i < 32; i += 8)
        dst[(long)(bx + ty + i) * R + by + tx] = __float2half(tile[tx][ty + i]);
}

// ---------------------------------------------------------------------------
// Transpose fp16 -> fp16 (V), per-z slab R x C
// ---------------------------------------------------------------------------
__global__ __launch_bounds__(256)
void transpose_h_kernel(const __half* __restrict__ src,
                        __half* __restrict__ dst, int R, int C)
{
    __shared__ __half tile[32][33];
    const long z = blockIdx.z;
    src += z * (long)R * C;
    dst += z * (long)R * C;
    const int bx = blockIdx.x * 32;
    const int by = blockIdx.y * 32;
    const int tx = threadIdx.x, ty = threadIdx.y;
#pragma unroll
    for (int i = 0; i < 32; i += 8)
        tile[ty + i][tx] = src[(long)(by + ty + i) * C + bx + tx];
    __syncthreads();
#pragma unroll
    for (int i = 0; i < 32; i += 8)
        dst[(long)(bx + ty + i) * R + by + tx] = tile[tx][ty + i];
}

// ---------------------------------------------------------------------------
// Row softmax (rows of 2048), in-place fp32 + fp16 copy
// ---------------------------------------------------------------------------
__global__ __launch_bounds__(256)
void softmax_kernel(float* __restrict__ attn, __half* __restrict__ pout)
{
    const long row = blockIdx.x;
    float* p = attn + row * (long)SEQ;
    __half* q = pout + row * (long)SEQ;
    const int t = threadIdx.x;

    float v[8];
    float m = -INFINITY;
#pragma unroll
    for (int i = 0; i < 8; i++) { v[i] = p[t + i * 256]; m = fmaxf(m, v[i]); }

    __shared__ float sh[8];
    const int lane = t & 31, warp = t >> 5;
#pragma unroll
    for (int o = 16; o; o >>= 1) m = fmaxf(m, __shfl_xor_sync(0xffffffffu, m, o));
    if (lane == 0) sh[warp] = m;
    __syncthreads();
    float bm = sh[0];
#pragma unroll
    for (int i = 1; i < 8; i++) bm = fmaxf(bm, sh[i]);
    __syncthreads();

    float s = 0.f;
#pragma unroll
    for (int i = 0; i < 8; i++) { v[i] = __expf(v[i] - bm); s += v[i]; }
#pragma unroll
    for (int o = 16; o; o >>= 1) s += __shfl_xor_sync(0xffffffffu, s, o);
    if (lane == 0) sh[warp] = s;
    __syncthreads();
    float bs = 0.f;
#pragma unroll
    for (int i = 0; i < 8; i++) bs += sh[i];

    const float inv = 1.0f / bs;
#pragma unroll
    for (int i = 0; i < 8; i++) {
        const float r = v[i] * inv;
        p[t + i * 256] = r;
        q[t + i * 256] = __float2half(r);
    }
}

// ---------------------------------------------------------------------------
// LayerNorm: one 128-thread block per row of 512
// ---------------------------------------------------------------------------
__global__ __launch_bounds__(128)
void layernorm_kernel(const float* __restrict__ ypre,
                      const float* __restrict__ gamma,
                      const float* __restrict__ beta,
                      float* __restrict__ out)
{
    const long row = blockIdx.x;
    const int t = threadIdx.x;
    const float4 v = reinterpret_cast<const float4*>(ypre + row * DIM)[t];

    float s  = v.x + v.y + v.z + v.w;
    float ss = v.x * v.x + v.y * v.y + v.z * v.z + v.w * v.w;

    __shared__ float shs[4], shss[4];
    const int lane = t & 31, warp = t >> 5;
#pragma unroll
    for (int o = 16; o; o >>= 1) {
        s  += __shfl_xor_sync(0xffffffffu, s,  o);
        ss += __shfl_xor_sync(0xffffffffu, ss, o);
    }
    if (lane == 0) { shs[warp] = s; shss[warp] = ss; }
    __syncthreads();
    const float bsum = shs[0] + shs[1] + shs[2] + shs[3];
    const float bssq = shss[0] + shss[1] + shss[2] + shss[3];

    const float mean = bsum * (1.0f / DIM);
    const float var  = bssq * (1.0f / DIM) - mean * mean;
    const float inv  = rsqrtf(var + 1e-5f);

    const float4 g = reinterpret_cast<const float4*>(gamma)[t];
    const float4 b = reinterpret_cast<const float4*>(beta)[t];
    float4 o;
    o.x = (v.x - mean) * inv * g.x + b.x;
    o.y = (v.y - mean) * inv * g.y + b.y;
    o.z = (v.z - mean) * inv * g.z + b.z;
    o.w = (v.w - mean) * inv * g.w + b.w;
    reinterpret_cast<float4*>(out + row * DIM)[t] = o;
}

// ---------------------------------------------------------------------------
extern "C" void kernel_launch(void* const* d_in, const int* in_sizes, int n_in,
                              void* d_out, int out_size)
{
    const float* x     = (const float*)d_in[0];
    const float* Wq    = (const float*)d_in[1];
    const float* bq    = (const float*)d_in[2];
    const float* Wk    = (const float*)d_in[3];
    const float* bk    = (const float*)d_in[4];
    const float* Wv    = (const float*)d_in[5];
    const float* bv    = (const float*)d_in[6];
    const float* Wp    = (const float*)d_in[7];
    const float* bp    = (const float*)d_in[8];
    const float* gamma = (const float*)d_in[9];
    const float* beta  = (const float*)d_in[10];

    float* y_out = (float*)d_out;
    float* attn  = y_out + YSIZE;

    __half *xh, *q, *k, *v, *vt, *o, *p, *wt;
    float* gy;
    cudaGetSymbolAddress((void**)&xh, g_xh);
    cudaGetSymbolAddress((void**)&q,  g_q);
    cudaGetSymbolAddress((void**)&k,  g_k);
    cudaGetSymbolAddress((void**)&v,  g_v);
    cudaGetSymbolAddress((void**)&vt, g_vt);
    cudaGetSymbolAddress((void**)&o,  g_o);
    cudaGetSymbolAddress((void**)&p,  g_p);
    cudaGetSymbolAddress((void**)&wt, g_wt);
    cudaGetSymbolAddress((void**)&gy, g_y);
    __half* WqT = wt;
    __half* WkT = wt + DIM * DIM;
    __half* WvT = wt + 2 * DIM * DIM;
    __half* WpT = wt + 3 * DIM * DIM;

    cudaFuncSetAttribute(hgemm<false>,
                         cudaFuncAttributeMaxDynamicSharedMemorySize, SMEM_TOTAL);
    cudaFuncSetAttribute(hgemm<true>,
                         cudaFuncAttributeMaxDynamicSharedMemorySize, SMEM_TOTAL);

    const float inv_sqrt_h = 1.0f / sqrtf((float)DIM);

    // ---- x -> fp16; weights -> transposed fp16 ----
    cvt_h_kernel<<<(unsigned)(YSIZE / 4 / 256), 256>>>(x, xh, (long)YSIZE);
    {
        dim3 blk(32, 8), grd(DIM / 32, DIM / 32, 1);
        transpose_cvt_kernel<<<grd, blk>>>(Wq, WqT, DIM, DIM);
        transpose_cvt_kernel<<<grd, blk>>>(Wk, WkT, DIM, DIM);
        transpose_cvt_kernel<<<grd, blk>>>(Wv, WvT, DIM, DIM);
        transpose_cvt_kernel<<<grd, blk>>>(Wp, WpT, DIM, DIM);
    }

    // ---- QKV projections -> fp16 q,k,v ----
    {
        dim3 grid(DIM / 128, BS / 128, 1);
        hgemm<true><<<grid, 256, SMEM_TOTAL>>>(xh, WqT, q, DIM, DIM, 0, 0, 0, 1.f, bq, nullptr);
        hgemm<true><<<grid, 256, SMEM_TOTAL>>>(xh, WkT, k, DIM, DIM, 0, 0, 0, 1.f, bk, nullptr);
        hgemm<true><<<grid, 256, SMEM_TOTAL>>>(xh, WvT, v, DIM, DIM, 0, 0, 0, 1.f, bv, nullptr);
    }

    // ---- scores = Q @ K^T / sqrt(H) -> attn slab (fp32) ----
    {
        dim3 grid(SEQ / 128, SEQ / 128, BATCH);
        hgemm<false><<<grid, 256, SMEM_TOTAL>>>(q, k, attn, SEQ, DIM,
                                                (long)SEQ * DIM, (long)SEQ * DIM,
                                                (long)SEQ * SEQ,
                                                inv_sqrt_h, nullptr, nullptr);
    }

    // ---- softmax: fp32 in place + fp16 copy ----
    softmax_kernel<<<BATCH * SEQ, 256>>>(attn, p);

    // ---- V^T per batch (fp16) ----
    {
        dim3 blk(32, 8), grd(DIM / 32, SEQ / 32, BATCH);
        transpose_h_kernel<<<grd, blk>>>(v, vt, SEQ, DIM);
    }

    // ---- O = P @ V -> fp16 ----
    {
        dim3 grid(DIM / 128, SEQ / 128, BATCH);
        hgemm<true><<<grid, 256, SMEM_TOTAL>>>(p, vt, o, DIM, SEQ,
                                               (long)SEQ * SEQ, (long)SEQ * DIM,
                                               (long)SEQ * DIM,
                                               1.f, nullptr, nullptr);
    }

    // ---- Ypre = O @ Wp + bp + x (fp32, residual fused) ----
    {
        dim3 grid(DIM / 128, BS / 128, 1);
        hgemm<false><<<grid, 256, SMEM_TOTAL>>>(o, WpT, gy, DIM, DIM, 0, 0, 0,
                                                1.f, bp, x);
    }

    // ---- LayerNorm ----
    layernorm_kernel<<<BATCH * SEQ, 128>>>(gy, gamma, beta, y_out);
}